// round 15
// baseline (speedup 1.0000x reference)
#include <cuda_runtime.h>
#include <cuda_fp16.h>
#include <cstdint>

// Problem constants
#define BATCH 16
#define SEQ   2048
#define DIM   256
#define ATTN_SCALE 0.0625f   // 1/sqrt(256)

#define BKC 32      // K-chunk (elements)
#define SA  80      // A/B tile row stride bytes (64B data + 16B pad)
#define SV  272     // 128-col V tile row stride bytes (256B + 16B pad)

// Stage offsets, scores kernel (Qhi[128x32], Khi[128x32]) — 4-stage
#define SC_A   0
#define SC_BHI 10240
#define SC_STAGE 20480
#define SC_SMEM (4 * SC_STAGE)     // 81920 (4-stage, 2 CTAs/SM)

// Stage offsets, out kernel (E[128x32], Vhi[32x128]) — 3-stage, 3 CTAs/SM
#define OV_A   0
#define OV_VHI 10240
#define OV_STAGE 18944
#define OV_SMEM (3 * OV_STAGE)     // 56832

// Pre-converted fp16 operand buffers + softmax scratch (device globals)
__device__ __align__(256) __half g_qh[(size_t)BATCH * SEQ * DIM];   // 16MB
__device__ __align__(256) __half g_kh[(size_t)BATCH * SEQ * DIM];
__device__ __align__(256) __half g_vh[(size_t)BATCH * SEQ * DIM];
__device__ __align__(256) __half g_e [(size_t)BATCH * SEQ * SEQ];   // 134MB
__device__ float g_zpart[(size_t)BATCH * SEQ * 64];                 // 8MB
__device__ float g_invz[(size_t)BATCH * SEQ];
__device__ uint32_t g_mbits[(size_t)SEQ * 64];                      // 512KB bit mask

// ---------------------------------------------------------------------------
__device__ __forceinline__ uint32_t smem_u32(const void* p) {
    uint32_t a;
    asm("{ .reg .u64 t; cvta.to.shared.u64 t, %1; cvt.u32.u64 %0, t; }" : "=r"(a) : "l"(p));
    return a;
}

__device__ __forceinline__ void cpa16(uint32_t saddr, const void* gptr) {
    asm volatile("cp.async.cg.shared.global [%0], [%1], 16;"
                 :: "r"(saddr), "l"(__cvta_generic_to_global(gptr)) : "memory");
}
__device__ __forceinline__ void cpcommit() {
    asm volatile("cp.async.commit_group;" ::: "memory");
}
template<int N> __device__ __forceinline__ void cpwait() {
    asm volatile("cp.async.wait_group %0;" :: "n"(N) : "memory");
}

__device__ __forceinline__ void ldmx4(uint32_t& r0, uint32_t& r1, uint32_t& r2,
                                      uint32_t& r3, uint32_t addr) {
    asm volatile("ldmatrix.sync.aligned.m8n8.x4.shared.b16 {%0,%1,%2,%3}, [%4];"
                 : "=r"(r0), "=r"(r1), "=r"(r2), "=r"(r3) : "r"(addr));
}
__device__ __forceinline__ void ldmx4t(uint32_t& r0, uint32_t& r1, uint32_t& r2,
                                       uint32_t& r3, uint32_t addr) {
    asm volatile("ldmatrix.sync.aligned.m8n8.x4.trans.shared.b16 {%0,%1,%2,%3}, [%4];"
                 : "=r"(r0), "=r"(r1), "=r"(r2), "=r"(r3) : "r"(addr));
}

// m16n8k16 fp16 mma, fp32 accumulate
__device__ __forceinline__ void mma_f16(float c[4], const uint32_t a[4],
                                        uint32_t b0, uint32_t b1) {
    asm("mma.sync.aligned.m16n8k16.row.col.f32.f16.f16.f32 "
        "{%0,%1,%2,%3}, {%4,%5,%6,%7}, {%8,%9}, {%0,%1,%2,%3};"
        : "+f"(c[0]), "+f"(c[1]), "+f"(c[2]), "+f"(c[3])
        : "r"(a[0]), "r"(a[1]), "r"(a[2]), "r"(a[3]), "r"(b0), "r"(b1));
}

__device__ __forceinline__ void cvt4(float4 v, uint2& h) {
    __half2 a = __floats2half2_rn(v.x, v.y);
    __half2 b = __floats2half2_rn(v.z, v.w);
    h.x = *(uint32_t*)&a; h.y = *(uint32_t*)&b;
}

// ---------------------------------------------------------------------------
// Kernel 0a: convert Q -> Qhi; K -> Khi; V -> Vhi (single fp16 each).
// ---------------------------------------------------------------------------
__global__ __launch_bounds__(256)
void prep_kernel(const float* __restrict__ q, const float* __restrict__ k,
                 const float* __restrict__ v)
{
    size_t i = (size_t)blockIdx.x * 256 + threadIdx.x;   // float4 index
    float4 qv = ((const float4*)q)[i];
    uint2 qh; cvt4(qv, qh);
    ((uint2*)g_qh)[i] = qh;

    float4 kv = ((const float4*)k)[i];
    uint2 kh; cvt4(kv, kh);
    ((uint2*)g_kh)[i] = kh;

    float4 vv = ((const float4*)v)[i];
    uint2 vh; cvt4(vv, vh);
    ((uint2*)g_vh)[i] = vh;
}

// ---------------------------------------------------------------------------
// Kernel 0b: pack mask (1,S,S) int32 0/1 -> bit table [S][64] uint32.
// ---------------------------------------------------------------------------
__global__ __launch_bounds__(256)
void maskpack_kernel(const int* __restrict__ mask)
{
    int w = blockIdx.x * 256 + threadIdx.x;     // 0 .. SEQ*64-1
    int row = w >> 6, wc = w & 63;
    const int4* mp = (const int4*)(mask + (size_t)row * SEQ + wc * 32);
    uint32_t bits = 0;
#pragma unroll
    for (int j = 0; j < 8; j++) {
        int4 v = mp[j];
        bits |= ((uint32_t)(v.x != 0)) << (j * 4 + 0);
        bits |= ((uint32_t)(v.y != 0)) << (j * 4 + 1);
        bits |= ((uint32_t)(v.z != 0)) << (j * 4 + 2);
        bits |= ((uint32_t)(v.w != 0)) << (j * 4 + 3);
    }
    g_mbits[w] = bits;
}

// ---------------------------------------------------------------------------
// Kernel 1: E = mask ? exp(scale * Q@K^T) : 0  -> g_e (fp16) + partial sums.
// Single-pass fp16, 4-stage cp.async pipeline, bit-mask epilogue.
// Grid (16,16,BATCH), 256 threads, tile 128x128, 2 CTAs/SM.
// ---------------------------------------------------------------------------
__device__ __forceinline__ void k1_issue(uint32_t stg, const __half* qrow,
                                         const __half* khrow, int k0, int tid) {
#pragma unroll
    for (int j = 0; j < 2; j++) {
        int o = tid + j * 256;
        int row = o >> 2, c = o & 3;
        size_t goff = (size_t)row * DIM + k0 + c * 8;
        uint32_t soff = (uint32_t)(row * SA + c * 16);
        cpa16(stg + SC_A   + soff, qrow  + goff);
        cpa16(stg + SC_BHI + soff, khrow + goff);
    }
}

__global__ __launch_bounds__(256, 2)
void scores_tc()
{
    extern __shared__ char smem[];
    const uint32_t sbase = smem_u32(smem);
    const int tid  = threadIdx.x;
    const int lane = tid & 31;
    const int wid  = tid >> 5;
    const int wm = wid & 1, wn = wid >> 1;
    const int g = lane >> 2, t = lane & 3;
    const int b  = blockIdx.z;
    const int m0 = blockIdx.y * 128;
    const int n0 = blockIdx.x * 128;

    const __half* qb  = g_qh + (size_t)b * SEQ * DIM + (size_t)m0 * DIM;
    const __half* kbh = g_kh + (size_t)b * SEQ * DIM + (size_t)n0 * DIM;

    const int mBase = wm * 64;
    const int nBase = wn * 32;
    const uint32_t aRowOff = (uint32_t)(mBase + (lane & 15)) * SA + ((lane >> 4) << 4);
    const uint32_t bRowOff = (uint32_t)(nBase + (lane & 7) + ((lane >> 4) << 3)) * SA
                           + (((lane >> 3) & 1) << 4);

    float acc[4][4][4];
#pragma unroll
    for (int i = 0; i < 4; i++)
#pragma unroll
        for (int j = 0; j < 4; j++)
#pragma unroll
            for (int c = 0; c < 4; c++) acc[i][j][c] = 0.0f;

    // 4-stage prologue: issue chunks 0,1,2
    k1_issue(sbase,                 qb, kbh, 0 * BKC, tid); cpcommit();
    k1_issue(sbase + 1 * SC_STAGE,  qb, kbh, 1 * BKC, tid); cpcommit();
    k1_issue(sbase + 2 * SC_STAGE,  qb, kbh, 2 * BKC, tid); cpcommit();

    const int NC = DIM / BKC;   // 8
    for (int c = 0; c < NC; c++) {
        // guarantee chunk c landed (tail ladder once issues stop)
        if (c >= NC - 1)      cpwait<0>();
        else if (c == NC - 2) cpwait<1>();
        else                  cpwait<2>();
        __syncthreads();
        // Issue chunk c+3 into stage (c+3)&3 == (c-1)&3 (readers passed barrier).
        if (c + 3 < NC) {
            k1_issue(sbase + ((c + 3) & 3) * SC_STAGE, qb, kbh, (c + 3) * BKC, tid);
            cpcommit();
        }
        const uint32_t stg = sbase + (c & 3) * SC_STAGE;
#pragma unroll
        for (int ks = 0; ks < 2; ks++) {
            const uint32_t kByte = (uint32_t)(ks * 32);
            uint32_t bh[4][2];
#pragma unroll
            for (int np = 0; np < 2; np++) {
                uint32_t addr = stg + SC_BHI + bRowOff + np * 16 * SA + kByte;
                uint32_t r0, r1, r2, r3;
                ldmx4(r0, r1, r2, r3, addr);
                bh[2*np][0] = r0; bh[2*np][1] = r1;
                bh[2*np+1][0] = r2; bh[2*np+1][1] = r3;
            }
#pragma unroll
            for (int mt = 0; mt < 4; mt++) {
                uint32_t addr = stg + SC_A + aRowOff + mt * 16 * SA + kByte;
                uint32_t ah[4];
                ldmx4(ah[0], ah[1], ah[2], ah[3], addr);
#pragma unroll
                for (int nt = 0; nt < 4; nt++) {
                    mma_f16(acc[mt][nt], ah, bh[nt][0], bh[nt][1]);
                }
            }
        }
    }

    // Epilogue: E = maskbit ? exp(scale*s) : 0 (fp16), plus partial row sums.
    __half* eb = g_e + (size_t)b * SEQ * SEQ;
    const int ztile = blockIdx.x * 4 + wn;
    const int word = (n0 + nBase) >> 5;        // one 32-bit mask word per warp col
#pragma unroll
    for (int mt = 0; mt < 4; mt++) {
        int r0 = m0 + mBase + mt * 16 + g;
        uint32_t w0 = g_mbits[r0 * 64 + word];
        uint32_t w1 = g_mbits[(r0 + 8) * 64 + word];
        float sum0 = 0.0f, sum1 = 0.0f;
#pragma unroll
        for (int nt = 0; nt < 4; nt++) {
            int col = n0 + nBase + nt * 8 + 2 * t;
            int bit = nt * 8 + 2 * t;
            float e00 = ((w0 >> bit) & 1u)       ? __expf(acc[mt][nt][0] * ATTN_SCALE) : 0.0f;
            float e01 = ((w0 >> (bit + 1)) & 1u) ? __expf(acc[mt][nt][1] * ATTN_SCALE) : 0.0f;
            float e10 = ((w1 >> bit) & 1u)       ? __expf(acc[mt][nt][2] * ATTN_SCALE) : 0.0f;
            float e11 = ((w1 >> (bit + 1)) & 1u) ? __expf(acc[mt][nt][3] * ATTN_SCALE) : 0.0f;
            sum0 += e00 + e01;
            sum1 += e10 + e11;
            __half2 p0 = __floats2half2_rn(e00, e01);
            __half2 p1 = __floats2half2_rn(e10, e11);
            *(__half2*)(eb + (size_t)r0 * SEQ + col) = p0;
            *(__half2*)(eb + (size_t)(r0 + 8) * SEQ + col) = p1;
        }
        sum0 += __shfl_xor_sync(0xFFFFFFFFu, sum0, 1);
        sum0 += __shfl_xor_sync(0xFFFFFFFFu, sum0, 2);
        sum1 += __shfl_xor_sync(0xFFFFFFFFu, sum1, 1);
        sum1 += __shfl_xor_sync(0xFFFFFFFFu, sum1, 2);
        if (t == 0) {
            g_zpart[((size_t)b * SEQ + r0) * 64 + ztile]     = sum0;
            g_zpart[((size_t)b * SEQ + r0 + 8) * 64 + ztile] = sum1;
        }
    }
}

// ---------------------------------------------------------------------------
// Kernel 2: invZ[row] = 1 / sum(zpart[row][0..63]).
// ---------------------------------------------------------------------------
__global__ __launch_bounds__(256)
void zreduce_kernel()
{
    int i = blockIdx.x * 256 + threadIdx.x;
    const float4* zp = (const float4*)(g_zpart + (size_t)i * 64);
    float s = 0.0f;
#pragma unroll
    for (int j = 0; j < 16; j++) {
        float4 v = zp[j];
        s += (v.x + v.y) + (v.z + v.w);
    }
    g_invz[i] = 1.0f / s;
}

// ---------------------------------------------------------------------------
// Kernel 3: O = (E @ Vhi) * invZ; BOTH x-CTAs write their 16-col half of
// attn = E * invZ per chunk, after the mma block.
// Grid (2,16,BATCH), 256 threads, tile 128x128, 3 CTAs/SM, 3-stage pipeline.
// ---------------------------------------------------------------------------
__device__ __forceinline__ void k3_issue(uint32_t stg, const __half* eb,
                                         const __half* vbh, int k0, int tid) {
#pragma unroll
    for (int j = 0; j < 2; j++) {
        int o = tid + j * 256;
        int erow = o >> 2, ec = o & 3;
        cpa16(stg + OV_A + erow * SA + ec * 16,
              eb + (size_t)erow * SEQ + k0 + ec * 8);
        int vrow = o >> 4, vc = o & 15;
        cpa16(stg + OV_VHI + vrow * SV + vc * 16,
              vbh + (size_t)(k0 + vrow) * DIM + vc * 8);
    }
}

__global__ __launch_bounds__(256, 3)
void out_fused(float* __restrict__ attn, float* __restrict__ o)
{
    extern __shared__ char smem[];
    const uint32_t sbase = smem_u32(smem);
    const int tid  = threadIdx.x;
    const int lane = tid & 31;
    const int wid  = tid >> 5;
    const int wm = wid & 1, wn = wid >> 1;
    const int g = lane >> 2, t = lane & 3;
    const int b  = blockIdx.z;
    const int m0 = blockIdx.y * 128;
    const int n0 = blockIdx.x * 128;
    const int phalf = blockIdx.x * 16;   // this CTA's 16-col half of each chunk

    const __half* eb  = g_e  + (size_t)b * SEQ * SEQ + (size_t)m0 * SEQ;
    const __half* vbh = g_vh + (size_t)b * SEQ * DIM + n0;
    float* pw = attn + (size_t)b * SEQ * SEQ + (size_t)m0 * SEQ;

    const int mBase = wm * 64;
    const int nBase = wn * 32;
    const uint32_t aRowOff = (uint32_t)(mBase + (lane & 15)) * SA + ((lane >> 4) << 4);
    const uint32_t vRow = (uint32_t)((lane & 7) + (((lane >> 3) & 1) << 3));
    const uint32_t vNOff = (uint32_t)(nBase + ((lane >> 4) << 3)) * 2;

    const int prow = tid >> 1;           // 0..127: P-write row (2 thr/row)
    const int ph   = tid & 1;            // 8-col quarter within this CTA's half
    const float izp = g_invz[(size_t)b * SEQ + m0 + prow];

    float acc[4][4][4];
#pragma unroll
    for (int i = 0; i < 4; i++)
#pragma unroll
        for (int j = 0; j < 4; j++)
#pragma unroll
            for (int c = 0; c < 4; c++) acc[i][j][c] = 0.0f;

    k3_issue(sbase, eb, vbh, 0, tid); cpcommit();
    k3_issue(sbase + OV_STAGE, eb, vbh, BKC, tid); cpcommit();

    const int NC = SEQ / BKC;   // 64
    int sc = 0;
    for (int c = 0; c < NC; c++) {
        if (c == NC - 1) cpwait<0>(); else cpwait<1>();
        __syncthreads();
        if (c + 2 < NC) {
            int sn = sc + 2; if (sn >= 3) sn -= 3;
            k3_issue(sbase + sn * OV_STAGE, eb, vbh, (c + 2) * BKC, tid);
            cpcommit();
        }
        const uint32_t stg = sbase + sc * OV_STAGE;

#pragma unroll
        for (int ks = 0; ks < 2; ks++) {
            uint32_t bh[4][2];
#pragma unroll
            for (int np = 0; np < 2; np++) {
                uint32_t addr = stg + OV_VHI + (ks * 16 + vRow) * SV + vNOff + np * 32;
                uint32_t r0, r1, r2, r3;
                ldmx4t(r0, r1, r2, r3, addr);
                bh[2*np][0] = r0; bh[2*np][1] = r1;
                bh[2*np+1][0] = r2; bh[2*np+1][1] = r3;
            }
#pragma unroll
            for (int mt = 0; mt < 4; mt++) {
                uint32_t addr = stg + OV_A + aRowOff + mt * 16 * SA + ks * 32;
                uint32_t ah[4];
                ldmx4(ah[0], ah[1], ah[2], ah[3], addr);
#pragma unroll
                for (int nt = 0; nt < 4; nt++) {
                    mma_f16(acc[mt][nt], ah, bh[nt][0], bh[nt][1]);
                }
            }
        }

        // Write this CTA's 16-col half of normalized P for chunk c (deferred:
        // stage sc stays valid until the issue after the NEXT barrier, and the
        // LDS below completes before that barrier).
        {
            const char* ep = smem + sc * OV_STAGE + OV_A + prow * SA
                           + (phalf + ph * 8) * 2;
            uint4 e4 = *(const uint4*)ep;           // 8 halfs
            __half2* hp = (__half2*)&e4;
            float2 f0 = __half22float2(hp[0]);
            float2 f1 = __half22float2(hp[1]);
            float2 f2 = __half22float2(hp[2]);
            float2 f3 = __half22float2(hp[3]);
            float* dst = pw + (size_t)prow * SEQ + c * BKC + phalf + ph * 8;
            *(float4*)dst =
                make_float4(f0.x * izp, f0.y * izp, f1.x * izp, f1.y * izp);
            *(float4*)(dst + 4) =
                make_float4(f2.x * izp, f2.y * izp, f3.x * izp, f3.y * izp);
        }

        sc++; if (sc == 3) sc = 0;
    }

    // Epilogue: O = acc * invZ[row]
    float* ob = o + (size_t)b * SEQ * DIM;
#pragma unroll
    for (int mt = 0; mt < 4; mt++) {
        int r0 = m0 + mBase + mt * 16 + g;
        float z0 = g_invz[(size_t)b * SEQ + r0];
        float z1 = g_invz[(size_t)b * SEQ + r0 + 8];
#pragma unroll
        for (int nt = 0; nt < 4; nt++) {
            int col = n0 + nBase + nt * 8 + 2 * t;
            *(float2*)(ob + (size_t)r0 * DIM + col) =
                make_float2(acc[mt][nt][0] * z0, acc[mt][nt][1] * z0);
            *(float2*)(ob + (size_t)(r0 + 8) * DIM + col) =
                make_float2(acc[mt][nt][2] * z1, acc[mt][nt][3] * z1);
        }
    }
}

// ---------------------------------------------------------------------------
extern "C" void kernel_launch(void* const* d_in, const int* in_sizes, int n_in,
                              void* d_out, int out_size)
{
    const float* q    = (const float*)d_in[0];
    const float* k    = (const float*)d_in[1];
    const float* v    = (const float*)d_in[2];
    const int*   mask = (const int*)d_in[3];

    float* out  = (float*)d_out;                      // [B, S, D]
    float* attn = out + (size_t)BATCH * SEQ * DIM;    // [B, S, S]

    cudaFuncSetAttribute(scores_tc, cudaFuncAttributeMaxDynamicSharedMemorySize, SC_SMEM);
    cudaFuncSetAttribute(out_fused, cudaFuncAttributeMaxDynamicSharedMemorySize, OV_SMEM);

    prep_kernel<<<(BATCH * SEQ * DIM / 4) / 256, 256>>>(q, k, v);
    maskpack_kernel<<<SEQ * 64 / 256, 256>>>(mask);
    scores_tc<<<dim3(SEQ / 128, SEQ / 128, BATCH), 256, SC_SMEM>>>();
    zreduce_kernel<<<BATCH * SEQ / 256, 256>>>();
    out_fused<<<dim3(2, SEQ / 128, BATCH), 256, OV_SMEM>>>(attn, out);
}

// round 16
// speedup vs baseline: 1.2119x; 1.2119x over previous
#include <cuda_runtime.h>
#include <cuda_fp16.h>
#include <cstdint>

// Problem constants
#define BATCH 16
#define SEQ   2048
#define DIM   256
#define ATTN_SCALE 0.0625f   // 1/sqrt(256)

#define BKC 32      // K-chunk (elements)
#define SA  80      // A/B tile row stride bytes (64B data + 16B pad)
#define SV  272     // 128-col V tile row stride bytes (256B + 16B pad)

// Stage offsets, scores kernel (Qhi[128x32], Khi[128x32]) — 3-stage (proven)
#define SC_A   0
#define SC_BHI 10240
#define SC_STAGE 20480
#define SC_SMEM (3 * SC_STAGE)     // 61440 (3-stage, 2 CTAs/SM)

// Stage offsets, out kernel (E[128x32], Vhi[32x128]) — 4-stage, 2 CTAs/SM
#define OV_A   0
#define OV_VHI 10240
#define OV_STAGE 18944
#define OV_SMEM (4 * OV_STAGE)     // 75776

// Pre-converted fp16 operand buffers + softmax scratch (device globals)
__device__ __align__(256) __half g_qh[(size_t)BATCH * SEQ * DIM];   // 16MB
__device__ __align__(256) __half g_kh[(size_t)BATCH * SEQ * DIM];
__device__ __align__(256) __half g_vh[(size_t)BATCH * SEQ * DIM];
__device__ __align__(256) __half g_e [(size_t)BATCH * SEQ * SEQ];   // 134MB
__device__ float g_zpart[(size_t)BATCH * SEQ * 64];                 // 8MB
__device__ float g_invz[(size_t)BATCH * SEQ];
__device__ uint32_t g_mbits[(size_t)SEQ * 64];                      // 512KB bit mask

// ---------------------------------------------------------------------------
__device__ __forceinline__ uint32_t smem_u32(const void* p) {
    uint32_t a;
    asm("{ .reg .u64 t; cvta.to.shared.u64 t, %1; cvt.u32.u64 %0, t; }" : "=r"(a) : "l"(p));
    return a;
}

__device__ __forceinline__ void cpa16(uint32_t saddr, const void* gptr) {
    asm volatile("cp.async.cg.shared.global [%0], [%1], 16;"
                 :: "r"(saddr), "l"(__cvta_generic_to_global(gptr)) : "memory");
}
__device__ __forceinline__ void cpcommit() {
    asm volatile("cp.async.commit_group;" ::: "memory");
}
template<int N> __device__ __forceinline__ void cpwait() {
    asm volatile("cp.async.wait_group %0;" :: "n"(N) : "memory");
}

__device__ __forceinline__ void ldmx4(uint32_t& r0, uint32_t& r1, uint32_t& r2,
                                      uint32_t& r3, uint32_t addr) {
    asm volatile("ldmatrix.sync.aligned.m8n8.x4.shared.b16 {%0,%1,%2,%3}, [%4];"
                 : "=r"(r0), "=r"(r1), "=r"(r2), "=r"(r3) : "r"(addr));
}
__device__ __forceinline__ void ldmx4t(uint32_t& r0, uint32_t& r1, uint32_t& r2,
                                       uint32_t& r3, uint32_t addr) {
    asm volatile("ldmatrix.sync.aligned.m8n8.x4.trans.shared.b16 {%0,%1,%2,%3}, [%4];"
                 : "=r"(r0), "=r"(r1), "=r"(r2), "=r"(r3) : "r"(addr));
}

// m16n8k16 fp16 mma, fp32 accumulate
__device__ __forceinline__ void mma_f16(float c[4], const uint32_t a[4],
                                        uint32_t b0, uint32_t b1) {
    asm("mma.sync.aligned.m16n8k16.row.col.f32.f16.f16.f32 "
        "{%0,%1,%2,%3}, {%4,%5,%6,%7}, {%8,%9}, {%0,%1,%2,%3};"
        : "+f"(c[0]), "+f"(c[1]), "+f"(c[2]), "+f"(c[3])
        : "r"(a[0]), "r"(a[1]), "r"(a[2]), "r"(a[3]), "r"(b0), "r"(b1));
}

__device__ __forceinline__ void cvt4(float4 v, uint2& h) {
    __half2 a = __floats2half2_rn(v.x, v.y);
    __half2 b = __floats2half2_rn(v.z, v.w);
    h.x = *(uint32_t*)&a; h.y = *(uint32_t*)&b;
}

// ---------------------------------------------------------------------------
// Kernel 0a: convert Q -> Qhi; K -> Khi; V -> Vhi (single fp16 each).
// ---------------------------------------------------------------------------
__global__ __launch_bounds__(256)
void prep_kernel(const float* __restrict__ q, const float* __restrict__ k,
                 const float* __restrict__ v)
{
    size_t i = (size_t)blockIdx.x * 256 + threadIdx.x;   // float4 index
    float4 qv = ((const float4*)q)[i];
    uint2 qh; cvt4(qv, qh);
    ((uint2*)g_qh)[i] = qh;

    float4 kv = ((const float4*)k)[i];
    uint2 kh; cvt4(kv, kh);
    ((uint2*)g_kh)[i] = kh;

    float4 vv = ((const float4*)v)[i];
    uint2 vh; cvt4(vv, vh);
    ((uint2*)g_vh)[i] = vh;
}

// ---------------------------------------------------------------------------
// Kernel 0b: pack mask (1,S,S) int32 0/1 -> bit table [S][64] uint32.
// ---------------------------------------------------------------------------
__global__ __launch_bounds__(256)
void maskpack_kernel(const int* __restrict__ mask)
{
    int w = blockIdx.x * 256 + threadIdx.x;     // 0 .. SEQ*64-1
    int row = w >> 6, wc = w & 63;
    const int4* mp = (const int4*)(mask + (size_t)row * SEQ + wc * 32);
    uint32_t bits = 0;
#pragma unroll
    for (int j = 0; j < 8; j++) {
        int4 v = mp[j];
        bits |= ((uint32_t)(v.x != 0)) << (j * 4 + 0);
        bits |= ((uint32_t)(v.y != 0)) << (j * 4 + 1);
        bits |= ((uint32_t)(v.z != 0)) << (j * 4 + 2);
        bits |= ((uint32_t)(v.w != 0)) << (j * 4 + 3);
    }
    g_mbits[w] = bits;
}

// ---------------------------------------------------------------------------
// Kernel 1: E = mask ? exp(scale * Q@K^T) : 0  -> g_e (fp16) + partial sums.
// Single-pass fp16, 3-stage cp.async pipeline (proven R14 config).
// Grid (16,16,BATCH), 256 threads, tile 128x128, 2 CTAs/SM.
// ---------------------------------------------------------------------------
__device__ __forceinline__ void k1_issue(uint32_t stg, const __half* qrow,
                                         const __half* khrow, int k0, int tid) {
#pragma unroll
    for (int j = 0; j < 2; j++) {
        int o = tid + j * 256;
        int row = o >> 2, c = o & 3;
        size_t goff = (size_t)row * DIM + k0 + c * 8;
        uint32_t soff = (uint32_t)(row * SA + c * 16);
        cpa16(stg + SC_A   + soff, qrow  + goff);
        cpa16(stg + SC_BHI + soff, khrow + goff);
    }
}

__global__ __launch_bounds__(256, 2)
void scores_tc()
{
    extern __shared__ char smem[];
    const uint32_t sbase = smem_u32(smem);
    const int tid  = threadIdx.x;
    const int lane = tid & 31;
    const int wid  = tid >> 5;
    const int wm = wid & 1, wn = wid >> 1;
    const int g = lane >> 2, t = lane & 3;
    const int b  = blockIdx.z;
    const int m0 = blockIdx.y * 128;
    const int n0 = blockIdx.x * 128;

    const __half* qb  = g_qh + (size_t)b * SEQ * DIM + (size_t)m0 * DIM;
    const __half* kbh = g_kh + (size_t)b * SEQ * DIM + (size_t)n0 * DIM;

    const int mBase = wm * 64;
    const int nBase = wn * 32;
    const uint32_t aRowOff = (uint32_t)(mBase + (lane & 15)) * SA + ((lane >> 4) << 4);
    const uint32_t bRowOff = (uint32_t)(nBase + (lane & 7) + ((lane >> 4) << 3)) * SA
                           + (((lane >> 3) & 1) << 4);

    float acc[4][4][4];
#pragma unroll
    for (int i = 0; i < 4; i++)
#pragma unroll
        for (int j = 0; j < 4; j++)
#pragma unroll
            for (int c = 0; c < 4; c++) acc[i][j][c] = 0.0f;

    k1_issue(sbase, qb, kbh, 0, tid); cpcommit();
    k1_issue(sbase + SC_STAGE, qb, kbh, BKC, tid); cpcommit();

    const int NC = DIM / BKC;   // 8
    int sc = 0;
    for (int c = 0; c < NC; c++) {
        if (c == NC - 1) cpwait<0>(); else cpwait<1>();
        __syncthreads();
        if (c + 2 < NC) {
            int sn = sc + 2; if (sn >= 3) sn -= 3;
            k1_issue(sbase + sn * SC_STAGE, qb, kbh, (c + 2) * BKC, tid);
            cpcommit();
        }
        const uint32_t stg = sbase + sc * SC_STAGE;
#pragma unroll
        for (int ks = 0; ks < 2; ks++) {
            const uint32_t kByte = (uint32_t)(ks * 32);
            uint32_t bh[4][2];
#pragma unroll
            for (int np = 0; np < 2; np++) {
                uint32_t addr = stg + SC_BHI + bRowOff + np * 16 * SA + kByte;
                uint32_t r0, r1, r2, r3;
                ldmx4(r0, r1, r2, r3, addr);
                bh[2*np][0] = r0; bh[2*np][1] = r1;
                bh[2*np+1][0] = r2; bh[2*np+1][1] = r3;
            }
#pragma unroll
            for (int mt = 0; mt < 4; mt++) {
                uint32_t addr = stg + SC_A + aRowOff + mt * 16 * SA + kByte;
                uint32_t ah[4];
                ldmx4(ah[0], ah[1], ah[2], ah[3], addr);
#pragma unroll
                for (int nt = 0; nt < 4; nt++) {
                    mma_f16(acc[mt][nt], ah, bh[nt][0], bh[nt][1]);
                }
            }
        }
        sc++; if (sc == 3) sc = 0;
    }

    // Epilogue: E = maskbit ? exp(scale*s) : 0 (fp16), plus partial row sums.
    __half* eb = g_e + (size_t)b * SEQ * SEQ;
    const int ztile = blockIdx.x * 4 + wn;
    const int word = (n0 + nBase) >> 5;        // one 32-bit mask word per warp col
#pragma unroll
    for (int mt = 0; mt < 4; mt++) {
        int r0 = m0 + mBase + mt * 16 + g;
        uint32_t w0 = g_mbits[r0 * 64 + word];
        uint32_t w1 = g_mbits[(r0 + 8) * 64 + word];
        float sum0 = 0.0f, sum1 = 0.0f;
#pragma unroll
        for (int nt = 0; nt < 4; nt++) {
            int col = n0 + nBase + nt * 8 + 2 * t;
            int bit = nt * 8 + 2 * t;
            float e00 = ((w0 >> bit) & 1u)       ? __expf(acc[mt][nt][0] * ATTN_SCALE) : 0.0f;
            float e01 = ((w0 >> (bit + 1)) & 1u) ? __expf(acc[mt][nt][1] * ATTN_SCALE) : 0.0f;
            float e10 = ((w1 >> bit) & 1u)       ? __expf(acc[mt][nt][2] * ATTN_SCALE) : 0.0f;
            float e11 = ((w1 >> (bit + 1)) & 1u) ? __expf(acc[mt][nt][3] * ATTN_SCALE) : 0.0f;
            sum0 += e00 + e01;
            sum1 += e10 + e11;
            __half2 p0 = __floats2half2_rn(e00, e01);
            __half2 p1 = __floats2half2_rn(e10, e11);
            *(__half2*)(eb + (size_t)r0 * SEQ + col) = p0;
            *(__half2*)(eb + (size_t)(r0 + 8) * SEQ + col) = p1;
        }
        sum0 += __shfl_xor_sync(0xFFFFFFFFu, sum0, 1);
        sum0 += __shfl_xor_sync(0xFFFFFFFFu, sum0, 2);
        sum1 += __shfl_xor_sync(0xFFFFFFFFu, sum1, 1);
        sum1 += __shfl_xor_sync(0xFFFFFFFFu, sum1, 2);
        if (t == 0) {
            g_zpart[((size_t)b * SEQ + r0) * 64 + ztile]     = sum0;
            g_zpart[((size_t)b * SEQ + r0 + 8) * 64 + ztile] = sum1;
        }
    }
}

// ---------------------------------------------------------------------------
// Kernel 2: invZ[row] = 1 / sum(zpart[row][0..63]).
// ---------------------------------------------------------------------------
__global__ __launch_bounds__(256)
void zreduce_kernel()
{
    int i = blockIdx.x * 256 + threadIdx.x;
    const float4* zp = (const float4*)(g_zpart + (size_t)i * 64);
    float s = 0.0f;
#pragma unroll
    for (int j = 0; j < 16; j++) {
        float4 v = zp[j];
        s += (v.x + v.y) + (v.z + v.w);
    }
    g_invz[i] = 1.0f / s;
}

// ---------------------------------------------------------------------------
// Kernel 3: O = (E @ Vhi) * invZ; BOTH x-CTAs write their 16-col half of
// attn = E * invZ per chunk, after the mma block.
// Grid (2,16,BATCH), 256 threads, tile 128x128, 2 CTAs/SM, 4-STAGE pipeline.
// ---------------------------------------------------------------------------
__device__ __forceinline__ void k3_issue(uint32_t stg, const __half* eb,
                                         const __half* vbh, int k0, int tid) {
#pragma unroll
    for (int j = 0; j < 2; j++) {
        int o = tid + j * 256;
        int erow = o >> 2, ec = o & 3;
        cpa16(stg + OV_A + erow * SA + ec * 16,
              eb + (size_t)erow * SEQ + k0 + ec * 8);
        int vrow = o >> 4, vc = o & 15;
        cpa16(stg + OV_VHI + vrow * SV + vc * 16,
              vbh + (size_t)(k0 + vrow) * DIM + vc * 8);
    }
}

__global__ __launch_bounds__(256, 2)
void out_fused(float* __restrict__ attn, float* __restrict__ o)
{
    extern __shared__ char smem[];
    const uint32_t sbase = smem_u32(smem);
    const int tid  = threadIdx.x;
    const int lane = tid & 31;
    const int wid  = tid >> 5;
    const int wm = wid & 1, wn = wid >> 1;
    const int g = lane >> 2, t = lane & 3;
    const int b  = blockIdx.z;
    const int m0 = blockIdx.y * 128;
    const int n0 = blockIdx.x * 128;
    const int phalf = blockIdx.x * 16;   // this CTA's 16-col half of each chunk

    const __half* eb  = g_e  + (size_t)b * SEQ * SEQ + (size_t)m0 * SEQ;
    const __half* vbh = g_vh + (size_t)b * SEQ * DIM + n0;
    float* pw = attn + (size_t)b * SEQ * SEQ + (size_t)m0 * SEQ;

    const int mBase = wm * 64;
    const int nBase = wn * 32;
    const uint32_t aRowOff = (uint32_t)(mBase + (lane & 15)) * SA + ((lane >> 4) << 4);
    const uint32_t vRow = (uint32_t)((lane & 7) + (((lane >> 3) & 1) << 3));
    const uint32_t vNOff = (uint32_t)(nBase + ((lane >> 4) << 3)) * 2;

    const int prow = tid >> 1;           // 0..127: P-write row (2 thr/row)
    const int ph   = tid & 1;            // 8-col quarter within this CTA's half
    const float izp = g_invz[(size_t)b * SEQ + m0 + prow];

    float acc[4][4][4];
#pragma unroll
    for (int i = 0; i < 4; i++)
#pragma unroll
        for (int j = 0; j < 4; j++)
#pragma unroll
            for (int c = 0; c < 4; c++) acc[i][j][c] = 0.0f;

    // 4-stage prologue: issue chunks 0,1,2
    k3_issue(sbase,                eb, vbh, 0 * BKC, tid); cpcommit();
    k3_issue(sbase + 1 * OV_STAGE, eb, vbh, 1 * BKC, tid); cpcommit();
    k3_issue(sbase + 2 * OV_STAGE, eb, vbh, 2 * BKC, tid); cpcommit();

    const int NC = SEQ / BKC;   // 64
    for (int c = 0; c < NC; c++) {
        // tail ladder: guarantee chunk c landed once issuing stops
        if (c >= NC - 1)      cpwait<0>();
        else if (c == NC - 2) cpwait<1>();
        else                  cpwait<2>();
        __syncthreads();
        // Issue chunk c+3 into stage (c+3)&3 == (c-1)&3 (readers passed barrier;
        // that stage's P-write LDS also completed before this barrier).
        if (c + 3 < NC) {
            k3_issue(sbase + ((c + 3) & 3) * OV_STAGE, eb, vbh, (c + 3) * BKC, tid);
            cpcommit();
        }
        const uint32_t stg = sbase + (c & 3) * OV_STAGE;

#pragma unroll
        for (int ks = 0; ks < 2; ks++) {
            uint32_t bh[4][2];
#pragma unroll
            for (int np = 0; np < 2; np++) {
                uint32_t addr = stg + OV_VHI + (ks * 16 + vRow) * SV + vNOff + np * 32;
                uint32_t r0, r1, r2, r3;
                ldmx4t(r0, r1, r2, r3, addr);
                bh[2*np][0] = r0; bh[2*np][1] = r1;
                bh[2*np+1][0] = r2; bh[2*np+1][1] = r3;
            }
#pragma unroll
            for (int mt = 0; mt < 4; mt++) {
                uint32_t addr = stg + OV_A + aRowOff + mt * 16 * SA + ks * 32;
                uint32_t ah[4];
                ldmx4(ah[0], ah[1], ah[2], ah[3], addr);
#pragma unroll
                for (int nt = 0; nt < 4; nt++) {
                    mma_f16(acc[mt][nt], ah, bh[nt][0], bh[nt][1]);
                }
            }
        }

        // Write this CTA's 16-col half of normalized P for chunk c (deferred;
        // stage (c&3) is not overwritten until after the NEXT barrier).
        {
            const char* ep = smem + (c & 3) * OV_STAGE + OV_A + prow * SA
                           + (phalf + ph * 8) * 2;
            uint4 e4 = *(const uint4*)ep;           // 8 halfs
            __half2* hp = (__half2*)&e4;
            float2 f0 = __half22float2(hp[0]);
            float2 f1 = __half22float2(hp[1]);
            float2 f2 = __half22float2(hp[2]);
            float2 f3 = __half22float2(hp[3]);
            float* dst = pw + (size_t)prow * SEQ + c * BKC + phalf + ph * 8;
            *(float4*)dst =
                make_float4(f0.x * izp, f0.y * izp, f1.x * izp, f1.y * izp);
            *(float4*)(dst + 4) =
                make_float4(f2.x * izp, f2.y * izp, f3.x * izp, f3.y * izp);
        }
    }

    // Epilogue: O = acc * invZ[row]
    float* ob = o + (size_t)b * SEQ * DIM;
#pragma unroll
    for (int mt = 0; mt < 4; mt++) {
        int r0 = m0 + mBase + mt * 16 + g;
        float z0 = g_invz[(size_t)b * SEQ + r0];
        float z1 = g_invz[(size_t)b * SEQ + r0 + 8];
#pragma unroll
        for (int nt = 0; nt < 4; nt++) {
            int col = n0 + nBase + nt * 8 + 2 * t;
            *(float2*)(ob + (size_t)r0 * DIM + col) =
                make_float2(acc[mt][nt][0] * z0, acc[mt][nt][1] * z0);
            *(float2*)(ob + (size_t)(r0 + 8) * DIM + col) =
                make_float2(acc[mt][nt][2] * z1, acc[mt][nt][3] * z1);
        }
    }
}

// ---------------------------------------------------------------------------
extern "C" void kernel_launch(void* const* d_in, const int* in_sizes, int n_in,
                              void* d_out, int out_size)
{
    const float* q    = (const float*)d_in[0];
    const float* k    = (const float*)d_in[1];
    const float* v    = (const float*)d_in[2];
    const int*   mask = (const int*)d_in[3];

    float* out  = (float*)d_out;                      // [B, S, D]
    float* attn = out + (size_t)BATCH * SEQ * DIM;    // [B, S, S]

    cudaFuncSetAttribute(scores_tc, cudaFuncAttributeMaxDynamicSharedMemorySize, SC_SMEM);
    cudaFuncSetAttribute(out_fused, cudaFuncAttributeMaxDynamicSharedMemorySize, OV_SMEM);

    prep_kernel<<<(BATCH * SEQ * DIM / 4) / 256, 256>>>(q, k, v);
    maskpack_kernel<<<SEQ * 64 / 256, 256>>>(mask);
    scores_tc<<<dim3(SEQ / 128, SEQ / 128, BATCH), 256, SC_SMEM>>>();
    zreduce_kernel<<<BATCH * SEQ / 256, 256>>>();
    out_fused<<<dim3(2, SEQ / 128, BATCH), 256, OV_SMEM>>>(attn, out);
}

// round 17
// speedup vs baseline: 1.2276x; 1.0130x over previous
#include <cuda_runtime.h>
#include <cuda_fp16.h>
#include <cstdint>

// Problem constants
#define BATCH 16
#define SEQ   2048
#define DIM   256
#define ATTN_SCALE 0.0625f   // 1/sqrt(256)

#define BKC 32      // K-chunk, scores kernel
#define BKO 64      // K-chunk, out kernel (this round's experiment)
#define SA  80      // 32-col tile row stride bytes (64B data + 16B pad)
#define SA2 144     // 64-col tile row stride bytes (128B data + 16B pad)
#define SV  272     // 128-col V tile row stride bytes (256B + 16B pad)

// Stage offsets, scores kernel (Qhi[128x32], Khi[128x32]) — 3-stage (proven R14)
#define SC_A   0
#define SC_BHI 10240
#define SC_STAGE 20480
#define SC_SMEM (3 * SC_STAGE)     // 61440 (2 CTAs/SM)

// Stage offsets, out kernel (E[128x64] @SA2, Vhi[64x128] @SV) — 3-stage
#define OV_A   0
#define OV_VHI 18432               // 128*144
#define OV_STAGE 35840             // 18432 + 64*272
#define OV_SMEM (3 * OV_STAGE)     // 107520 (2 CTAs/SM: 215KB <= 227KB)

// Pre-converted fp16 operand buffers + softmax scratch (device globals)
__device__ __align__(256) __half g_qh[(size_t)BATCH * SEQ * DIM];   // 16MB
__device__ __align__(256) __half g_kh[(size_t)BATCH * SEQ * DIM];
__device__ __align__(256) __half g_vh[(size_t)BATCH * SEQ * DIM];
__device__ __align__(256) __half g_e [(size_t)BATCH * SEQ * SEQ];   // 134MB
__device__ float g_zpart[(size_t)BATCH * SEQ * 64];                 // 8MB
__device__ float g_invz[(size_t)BATCH * SEQ];
__device__ uint32_t g_mbits[(size_t)SEQ * 64];                      // 512KB bit mask

// ---------------------------------------------------------------------------
__device__ __forceinline__ uint32_t smem_u32(const void* p) {
    uint32_t a;
    asm("{ .reg .u64 t; cvta.to.shared.u64 t, %1; cvt.u32.u64 %0, t; }" : "=r"(a) : "l"(p));
    return a;
}

__device__ __forceinline__ void cpa16(uint32_t saddr, const void* gptr) {
    asm volatile("cp.async.cg.shared.global [%0], [%1], 16;"
                 :: "r"(saddr), "l"(__cvta_generic_to_global(gptr)) : "memory");
}
__device__ __forceinline__ void cpcommit() {
    asm volatile("cp.async.commit_group;" ::: "memory");
}
template<int N> __device__ __forceinline__ void cpwait() {
    asm volatile("cp.async.wait_group %0;" :: "n"(N) : "memory");
}

__device__ __forceinline__ void ldmx4(uint32_t& r0, uint32_t& r1, uint32_t& r2,
                                      uint32_t& r3, uint32_t addr) {
    asm volatile("ldmatrix.sync.aligned.m8n8.x4.shared.b16 {%0,%1,%2,%3}, [%4];"
                 : "=r"(r0), "=r"(r1), "=r"(r2), "=r"(r3) : "r"(addr));
}
__device__ __forceinline__ void ldmx4t(uint32_t& r0, uint32_t& r1, uint32_t& r2,
                                       uint32_t& r3, uint32_t addr) {
    asm volatile("ldmatrix.sync.aligned.m8n8.x4.trans.shared.b16 {%0,%1,%2,%3}, [%4];"
                 : "=r"(r0), "=r"(r1), "=r"(r2), "=r"(r3) : "r"(addr));
}

// m16n8k16 fp16 mma, fp32 accumulate
__device__ __forceinline__ void mma_f16(float c[4], const uint32_t a[4],
                                        uint32_t b0, uint32_t b1) {
    asm("mma.sync.aligned.m16n8k16.row.col.f32.f16.f16.f32 "
        "{%0,%1,%2,%3}, {%4,%5,%6,%7}, {%8,%9}, {%0,%1,%2,%3};"
        : "+f"(c[0]), "+f"(c[1]), "+f"(c[2]), "+f"(c[3])
        : "r"(a[0]), "r"(a[1]), "r"(a[2]), "r"(a[3]), "r"(b0), "r"(b1));
}

__device__ __forceinline__ void cvt4(float4 v, uint2& h) {
    __half2 a = __floats2half2_rn(v.x, v.y);
    __half2 b = __floats2half2_rn(v.z, v.w);
    h.x = *(uint32_t*)&a; h.y = *(uint32_t*)&b;
}

// ---------------------------------------------------------------------------
// Kernel 0a: convert Q -> Qhi; K -> Khi; V -> Vhi (single fp16 each).
// ---------------------------------------------------------------------------
__global__ __launch_bounds__(256)
void prep_kernel(const float* __restrict__ q, const float* __restrict__ k,
                 const float* __restrict__ v)
{
    size_t i = (size_t)blockIdx.x * 256 + threadIdx.x;   // float4 index
    float4 qv = ((const float4*)q)[i];
    uint2 qh; cvt4(qv, qh);
    ((uint2*)g_qh)[i] = qh;

    float4 kv = ((const float4*)k)[i];
    uint2 kh; cvt4(kv, kh);
    ((uint2*)g_kh)[i] = kh;

    float4 vv = ((const float4*)v)[i];
    uint2 vh; cvt4(vv, vh);
    ((uint2*)g_vh)[i] = vh;
}

// ---------------------------------------------------------------------------
// Kernel 0b: pack mask (1,S,S) int32 0/1 -> bit table [S][64] uint32.
// ---------------------------------------------------------------------------
__global__ __launch_bounds__(256)
void maskpack_kernel(const int* __restrict__ mask)
{
    int w = blockIdx.x * 256 + threadIdx.x;     // 0 .. SEQ*64-1
    int row = w >> 6, wc = w & 63;
    const int4* mp = (const int4*)(mask + (size_t)row * SEQ + wc * 32);
    uint32_t bits = 0;
#pragma unroll
    for (int j = 0; j < 8; j++) {
        int4 v = mp[j];
        bits |= ((uint32_t)(v.x != 0)) << (j * 4 + 0);
        bits |= ((uint32_t)(v.y != 0)) << (j * 4 + 1);
        bits |= ((uint32_t)(v.z != 0)) << (j * 4 + 2);
        bits |= ((uint32_t)(v.w != 0)) << (j * 4 + 3);
    }
    g_mbits[w] = bits;
}

// ---------------------------------------------------------------------------
// Kernel 1: E = mask ? exp(scale * Q@K^T) : 0  -> g_e (fp16) + partial sums.
// Single-pass fp16, 3-stage cp.async pipeline (exact R14 config).
// Grid (16,16,BATCH), 256 threads, tile 128x128, 2 CTAs/SM.
// ---------------------------------------------------------------------------
__device__ __forceinline__ void k1_issue(uint32_t stg, const __half* qrow,
                                         const __half* khrow, int k0, int tid) {
#pragma unroll
    for (int j = 0; j < 2; j++) {
        int o = tid + j * 256;
        int row = o >> 2, c = o & 3;
        size_t goff = (size_t)row * DIM + k0 + c * 8;
        uint32_t soff = (uint32_t)(row * SA + c * 16);
        cpa16(stg + SC_A   + soff, qrow  + goff);
        cpa16(stg + SC_BHI + soff, khrow + goff);
    }
}

__global__ __launch_bounds__(256, 2)
void scores_tc()
{
    extern __shared__ char smem[];
    const uint32_t sbase = smem_u32(smem);
    const int tid  = threadIdx.x;
    const int lane = tid & 31;
    const int wid  = tid >> 5;
    const int wm = wid & 1, wn = wid >> 1;
    const int g = lane >> 2, t = lane & 3;
    const int b  = blockIdx.z;
    const int m0 = blockIdx.y * 128;
    const int n0 = blockIdx.x * 128;

    const __half* qb  = g_qh + (size_t)b * SEQ * DIM + (size_t)m0 * DIM;
    const __half* kbh = g_kh + (size_t)b * SEQ * DIM + (size_t)n0 * DIM;

    const int mBase = wm * 64;
    const int nBase = wn * 32;
    const uint32_t aRowOff = (uint32_t)(mBase + (lane & 15)) * SA + ((lane >> 4) << 4);
    const uint32_t bRowOff = (uint32_t)(nBase + (lane & 7) + ((lane >> 4) << 3)) * SA
                           + (((lane >> 3) & 1) << 4);

    float acc[4][4][4];
#pragma unroll
    for (int i = 0; i < 4; i++)
#pragma unroll
        for (int j = 0; j < 4; j++)
#pragma unroll
            for (int c = 0; c < 4; c++) acc[i][j][c] = 0.0f;

    k1_issue(sbase, qb, kbh, 0, tid); cpcommit();
    k1_issue(sbase + SC_STAGE, qb, kbh, BKC, tid); cpcommit();

    const int NC = DIM / BKC;   // 8
    int sc = 0;
    for (int c = 0; c < NC; c++) {
        if (c == NC - 1) cpwait<0>(); else cpwait<1>();
        __syncthreads();
        if (c + 2 < NC) {
            int sn = sc + 2; if (sn >= 3) sn -= 3;
            k1_issue(sbase + sn * SC_STAGE, qb, kbh, (c + 2) * BKC, tid);
            cpcommit();
        }
        const uint32_t stg = sbase + sc * SC_STAGE;
#pragma unroll
        for (int ks = 0; ks < 2; ks++) {
            const uint32_t kByte = (uint32_t)(ks * 32);
            uint32_t bh[4][2];
#pragma unroll
            for (int np = 0; np < 2; np++) {
                uint32_t addr = stg + SC_BHI + bRowOff + np * 16 * SA + kByte;
                uint32_t r0, r1, r2, r3;
                ldmx4(r0, r1, r2, r3, addr);
                bh[2*np][0] = r0; bh[2*np][1] = r1;
                bh[2*np+1][0] = r2; bh[2*np+1][1] = r3;
            }
#pragma unroll
            for (int mt = 0; mt < 4; mt++) {
                uint32_t addr = stg + SC_A + aRowOff + mt * 16 * SA + kByte;
                uint32_t ah[4];
                ldmx4(ah[0], ah[1], ah[2], ah[3], addr);
#pragma unroll
                for (int nt = 0; nt < 4; nt++) {
                    mma_f16(acc[mt][nt], ah, bh[nt][0], bh[nt][1]);
                }
            }
        }
        sc++; if (sc == 3) sc = 0;
    }

    // Epilogue: E = maskbit ? exp(scale*s) : 0 (fp16), plus partial row sums.
    __half* eb = g_e + (size_t)b * SEQ * SEQ;
    const int ztile = blockIdx.x * 4 + wn;
    const int word = (n0 + nBase) >> 5;
#pragma unroll
    for (int mt = 0; mt < 4; mt++) {
        int r0 = m0 + mBase + mt * 16 + g;
        uint32_t w0 = g_mbits[r0 * 64 + word];
        uint32_t w1 = g_mbits[(r0 + 8) * 64 + word];
        float sum0 = 0.0f, sum1 = 0.0f;
#pragma unroll
        for (int nt = 0; nt < 4; nt++) {
            int col = n0 + nBase + nt * 8 + 2 * t;
            int bit = nt * 8 + 2 * t;
            float e00 = ((w0 >> bit) & 1u)       ? __expf(acc[mt][nt][0] * ATTN_SCALE) : 0.0f;
            float e01 = ((w0 >> (bit + 1)) & 1u) ? __expf(acc[mt][nt][1] * ATTN_SCALE) : 0.0f;
            float e10 = ((w1 >> bit) & 1u)       ? __expf(acc[mt][nt][2] * ATTN_SCALE) : 0.0f;
            float e11 = ((w1 >> (bit + 1)) & 1u) ? __expf(acc[mt][nt][3] * ATTN_SCALE) : 0.0f;
            sum0 += e00 + e01;
            sum1 += e10 + e11;
            __half2 p0 = __floats2half2_rn(e00, e01);
            __half2 p1 = __floats2half2_rn(e10, e11);
            *(__half2*)(eb + (size_t)r0 * SEQ + col) = p0;
            *(__half2*)(eb + (size_t)(r0 + 8) * SEQ + col) = p1;
        }
        sum0 += __shfl_xor_sync(0xFFFFFFFFu, sum0, 1);
        sum0 += __shfl_xor_sync(0xFFFFFFFFu, sum0, 2);
        sum1 += __shfl_xor_sync(0xFFFFFFFFu, sum1, 1);
        sum1 += __shfl_xor_sync(0xFFFFFFFFu, sum1, 2);
        if (t == 0) {
            g_zpart[((size_t)b * SEQ + r0) * 64 + ztile]     = sum0;
            g_zpart[((size_t)b * SEQ + r0 + 8) * 64 + ztile] = sum1;
        }
    }
}

// ---------------------------------------------------------------------------
// Kernel 2: invZ[row] = 1 / sum(zpart[row][0..63]).
// ---------------------------------------------------------------------------
__global__ __launch_bounds__(256)
void zreduce_kernel()
{
    int i = blockIdx.x * 256 + threadIdx.x;
    const float4* zp = (const float4*)(g_zpart + (size_t)i * 64);
    float s = 0.0f;
#pragma unroll
    for (int j = 0; j < 16; j++) {
        float4 v = zp[j];
        s += (v.x + v.y) + (v.z + v.w);
    }
    g_invz[i] = 1.0f / s;
}

// ---------------------------------------------------------------------------
// Kernel 3: O = (E @ Vhi) * invZ; BOTH x-CTAs write their 32-col half of
// attn = E * invZ per chunk, after the mma block.
// BKO=64 chunks: 32 iterations (half the barriers of R14).
// Grid (2,16,BATCH), 256 threads, tile 128x128, 2 CTAs/SM, 3-stage pipeline.
// ---------------------------------------------------------------------------
__device__ __forceinline__ void k3_issue(uint32_t stg, const __half* eb,
                                         const __half* vbh, int k0, int tid) {
    // E tile: 128 rows x 64 halfs (128B/row) -> 4 x 256 cpa16
#pragma unroll
    for (int j = 0; j < 4; j++) {
        int o = tid + j * 256;
        int erow = o >> 3, ec = o & 7;
        cpa16(stg + OV_A + erow * SA2 + ec * 16,
              eb + (size_t)erow * SEQ + k0 + ec * 8);
        // V tile: 64 rows x 128 halfs (256B/row) -> 4 x 256 cpa16
        int vrow = o >> 4, vc = o & 15;
        cpa16(stg + OV_VHI + vrow * SV + vc * 16,
              vbh + (size_t)(k0 + vrow) * DIM + vc * 8);
    }
}

__global__ __launch_bounds__(256, 2)
void out_fused(float* __restrict__ attn, float* __restrict__ o)
{
    extern __shared__ char smem[];
    const uint32_t sbase = smem_u32(smem);
    const int tid  = threadIdx.x;
    const int lane = tid & 31;
    const int wid  = tid >> 5;
    const int wm = wid & 1, wn = wid >> 1;
    const int g = lane >> 2, t = lane & 3;
    const int b  = blockIdx.z;
    const int m0 = blockIdx.y * 128;
    const int n0 = blockIdx.x * 128;
    const int phalf = blockIdx.x * 32;   // this CTA's 32-col half of each chunk

    const __half* eb  = g_e  + (size_t)b * SEQ * SEQ + (size_t)m0 * SEQ;
    const __half* vbh = g_vh + (size_t)b * SEQ * DIM + n0;
    float* pw = attn + (size_t)b * SEQ * SEQ + (size_t)m0 * SEQ;

    const int mBase = wm * 64;
    const int nBase = wn * 32;
    const uint32_t aRowOff = (uint32_t)(mBase + (lane & 15)) * SA2 + ((lane >> 4) << 4);
    const uint32_t vRow = (uint32_t)((lane & 7) + (((lane >> 3) & 1) << 3));
    const uint32_t vNOff = (uint32_t)(nBase + ((lane >> 4) << 3)) * 2;

    const int prow = tid >> 1;           // 0..127: P-write row (2 thr/row)
    const int ph   = tid & 1;            // 16-col quarter within this CTA's half
    const float izp = g_invz[(size_t)b * SEQ + m0 + prow];

    float acc[4][4][4];
#pragma unroll
    for (int i = 0; i < 4; i++)
#pragma unroll
        for (int j = 0; j < 4; j++)
#pragma unroll
            for (int c = 0; c < 4; c++) acc[i][j][c] = 0.0f;

    k3_issue(sbase, eb, vbh, 0, tid); cpcommit();
    k3_issue(sbase + OV_STAGE, eb, vbh, BKO, tid); cpcommit();

    const int NC = SEQ / BKO;   // 32
    int sc = 0;
    for (int c = 0; c < NC; c++) {
        if (c == NC - 1) cpwait<0>(); else cpwait<1>();
        __syncthreads();
        if (c + 2 < NC) {
            int sn = sc + 2; if (sn >= 3) sn -= 3;
            k3_issue(sbase + sn * OV_STAGE, eb, vbh, (c + 2) * BKO, tid);
            cpcommit();
        }
        const uint32_t stg = sbase + sc * OV_STAGE;

#pragma unroll
        for (int ks = 0; ks < 4; ks++) {
            uint32_t bh[4][2];
#pragma unroll
            for (int np = 0; np < 2; np++) {
                uint32_t addr = stg + OV_VHI + (ks * 16 + vRow) * SV + vNOff + np * 32;
                uint32_t r0, r1, r2, r3;
                ldmx4t(r0, r1, r2, r3, addr);
                bh[2*np][0] = r0; bh[2*np][1] = r1;
                bh[2*np+1][0] = r2; bh[2*np+1][1] = r3;
            }
#pragma unroll
            for (int mt = 0; mt < 4; mt++) {
                uint32_t addr = stg + OV_A + aRowOff + mt * 16 * SA2 + ks * 32;
                uint32_t ah[4];
                ldmx4(ah[0], ah[1], ah[2], ah[3], addr);
#pragma unroll
                for (int nt = 0; nt < 4; nt++) {
                    mma_f16(acc[mt][nt], ah, bh[nt][0], bh[nt][1]);
                }
            }
        }

        // Write this CTA's 32-col half of normalized P for chunk c (deferred;
        // stage sc is not overwritten until after the NEXT barrier, and this
        // LDS completes before that barrier).
        {
            const char* ep = smem + sc * OV_STAGE + OV_A + prow * SA2
                           + (phalf + ph * 16) * 2;
            uint4 e4a = *(const uint4*)ep;           // 8 halfs
            uint4 e4b = *(const uint4*)(ep + 16);    // 8 halfs
            float* dst = pw + (size_t)prow * SEQ + c * BKO + phalf + ph * 16;
            __half2* ha = (__half2*)&e4a;
            __half2* hb = (__half2*)&e4b;
#pragma unroll
            for (int u = 0; u < 2; u++) {
                float2 f0 = __half22float2(ha[u * 2]);
                float2 f1 = __half22float2(ha[u * 2 + 1]);
                *(float4*)(dst + u * 4) =
                    make_float4(f0.x * izp, f0.y * izp, f1.x * izp, f1.y * izp);
                float2 f2 = __half22float2(hb[u * 2]);
                float2 f3 = __half22float2(hb[u * 2 + 1]);
                *(float4*)(dst + 8 + u * 4) =
                    make_float4(f2.x * izp, f2.y * izp, f3.x * izp, f3.y * izp);
            }
        }

        sc++; if (sc == 3) sc = 0;
    }

    // Epilogue: O = acc * invZ[row]
    float* ob = o + (size_t)b * SEQ * DIM;
#pragma unroll
    for (int mt = 0; mt < 4; mt++) {
        int r0 = m0 + mBase + mt * 16 + g;
        float z0 = g_invz[(size_t)b * SEQ + r0];
        float z1 = g_invz[(size_t)b * SEQ + r0 + 8];
#pragma unroll
        for (int nt = 0; nt < 4; nt++) {
            int col = n0 + nBase + nt * 8 + 2 * t;
            *(float2*)(ob + (size_t)r0 * DIM + col) =
                make_float2(acc[mt][nt][0] * z0, acc[mt][nt][1] * z0);
            *(float2*)(ob + (size_t)(r0 + 8) * DIM + col) =
                make_float2(acc[mt][nt][2] * z1, acc[mt][nt][3] * z1);
        }
    }
}

// ---------------------------------------------------------------------------
extern "C" void kernel_launch(void* const* d_in, const int* in_sizes, int n_in,
                              void* d_out, int out_size)
{
    const float* q    = (const float*)d_in[0];
    const float* k    = (const float*)d_in[1];
    const float* v    = (const float*)d_in[2];
    const int*   mask = (const int*)d_in[3];

    float* out  = (float*)d_out;                      // [B, S, D]
    float* attn = out + (size_t)BATCH * SEQ * DIM;    // [B, S, S]

    cudaFuncSetAttribute(scores_tc, cudaFuncAttributeMaxDynamicSharedMemorySize, SC_SMEM);
    cudaFuncSetAttribute(out_fused, cudaFuncAttributeMaxDynamicSharedMemorySize, OV_SMEM);

    prep_kernel<<<(BATCH * SEQ * DIM / 4) / 256, 256>>>(q, k, v);
    maskpack_kernel<<<SEQ * 64 / 256, 256>>>(mask);
    scores_tc<<<dim3(SEQ / 128, SEQ / 128, BATCH), 256, SC_SMEM>>>();
    zreduce_kernel<<<BATCH * SEQ / 256, 256>>>();
    out_fused<<<dim3(2, SEQ / 128, BATCH), 256, OV_SMEM>>>(attn, out);
}